// round 15
// baseline (speedup 1.0000x reference)
#include <cuda_runtime.h>
#include <cuda_bf16.h>
#include <math.h>
#include <stdint.h>
#include <string.h>

// ---------------- problem constants ----------------
#define Bb 4
#define Cc 256
#define Hh 80
#define Ww 80
#define Nq 300
#define IDim 128
#define HID 512
#define H2 160
#define W2 160
#define HW (Hh*Ww)
#define CHW (Cc*HW)

// ---------------- GEMM tile geometry ----------------
#define RS 40
#define RSB 72
#define STG_A_H 0
#define STG_A_L 10240
#define STG_B_H 20480
#define STG_B_L 25088
#define STG_SZ 29696
#define SMEMB (3*STG_SZ)

// ---------------- device scratch (f32) ----------------
__device__ float g_x[Bb*CHW];
__device__ float g_t[Bb*CHW];
__device__ float g_q4[Bb*Nq*IDim];
__device__ float g_off[Bb*Nq];
__device__ float g_m[Bb*Nq*HW];

// ---------------- device scratch (bf16 hi/lo planes) ----------------
__device__ __nv_bfloat16 g_pwh[2*Cc*Cc],  g_pwl[2*Cc*Cc];
__device__ __nv_bfloat16 g_w1h[Cc*HID],   g_w1l[Cc*HID];
__device__ __nv_bfloat16 g_w2h[HID*HID],  g_w2l[HID*HID];
__device__ __nv_bfloat16 g_w3h[HID*Cc],   g_w3l[HID*Cc];
__device__ __nv_bfloat16 g_qph[Cc*IDim],  g_qpl[Cc*IDim];
__device__ __nv_bfloat16 g_sph[IDim*Cc],  g_spl[IDim*Cc];
__device__ __nv_bfloat16 g_qfh[Bb*Nq*Cc], g_qfl[Bb*Nq*Cc];
__device__ __nv_bfloat16 g_o1h[Bb*Nq*HID],g_o1l[Bb*Nq*HID];
__device__ __nv_bfloat16 g_o2h[Bb*Nq*HID],g_o2l[Bb*Nq*HID];
__device__ __nv_bfloat16 g_o3h[Bb*Nq*Cc], g_o3l[Bb*Nq*Cc];
__device__ __nv_bfloat16 g_o4h[Bb*Nq*IDim],g_o4l[Bb*Nq*IDim];
__device__ __nv_bfloat16 g_qqh[Bb*Nq*Cc], g_qql[Bb*Nq*Cc];
__device__ __nv_bfloat16 g_bsh[Bb*CHW],   g_bsl[Bb*CHW];
__device__ __nv_bfloat16 g_ysh[Bb*CHW],   g_ysl[Bb*CHW];

__device__ __forceinline__ float gelu_f(float x) {
    return 0.5f * x * (1.0f + erff(x * 0.70710678118654752f));
}
__device__ __forceinline__ uint32_t su32(const void* p) {
    return (uint32_t)__cvta_generic_to_shared(p);
}
__device__ __forceinline__ void ldsm4(uint32_t* r, uint32_t addr) {
    asm volatile("ldmatrix.sync.aligned.m8n8.x4.shared.b16 {%0,%1,%2,%3}, [%4];"
        : "=r"(r[0]), "=r"(r[1]), "=r"(r[2]), "=r"(r[3]) : "r"(addr));
}
__device__ __forceinline__ void ldsm4t(uint32_t* r, uint32_t addr) {
    asm volatile("ldmatrix.sync.aligned.m8n8.x4.trans.shared.b16 {%0,%1,%2,%3}, [%4];"
        : "=r"(r[0]), "=r"(r[1]), "=r"(r[2]), "=r"(r[3]) : "r"(addr));
}
__device__ __forceinline__ void mma16816(float* d, const uint32_t* a, const uint32_t* b) {
    asm volatile("mma.sync.aligned.m16n8k16.row.col.f32.bf16.bf16.f32 "
        "{%0,%1,%2,%3}, {%4,%5,%6,%7}, {%8,%9}, {%0,%1,%2,%3};"
        : "+f"(d[0]), "+f"(d[1]), "+f"(d[2]), "+f"(d[3])
        : "r"(a[0]), "r"(a[1]), "r"(a[2]), "r"(a[3]), "r"(b[0]), "r"(b[1]));
}
__device__ __forceinline__ void split_bf16(float x, __nv_bfloat16& hi, __nv_bfloat16& lo) {
    hi = __float2bfloat16(x);
    lo = __float2bfloat16(x - __bfloat162float(hi));
}
__device__ __forceinline__ uint32_t pk2(__nv_bfloat16 a, __nv_bfloat16 b) {
    __nv_bfloat162 t(a, b);
    uint32_t u;
    memcpy(&u, &t, 4);
    return u;
}
__device__ __forceinline__ void cpa16(uint32_t d, const void* s, int bytes) {
    asm volatile("cp.async.cg.shared.global [%0], [%1], 16, %2;"
        :: "r"(d), "l"(s), "r"(bytes));
}
#define CP_COMMIT asm volatile("cp.async.commit_group;")
#define CP_WAIT1  asm volatile("cp.async.wait_group 1;")

// ---------------- depthwise 3x3 conv (SAME) + bias, one batch ----------------
__global__ void dw_kernel(const float* __restrict__ x, const float* __restrict__ w,
                          const float* __restrict__ bia, float* __restrict__ out)
{
    int wq = threadIdx.x;
    int hq = blockIdx.y * 4 + threadIdx.y;
    int c = blockIdx.z;
    const float* xp = x + (long)c * HW;
    const float* wp = w + c * 9;
    float w00 = wp[0], w01 = wp[1], w02 = wp[2];
    float w10 = wp[3], w11 = wp[4], w12 = wp[5];
    float w20 = wp[6], w21 = wp[7], w22 = wp[8];
    float acc = bia[c];

    const float* r0 = xp + (hq - 1) * Ww;
    const float* r1 = xp + hq * Ww;
    const float* r2 = xp + (hq + 1) * Ww;
    bool ht = hq > 0, hb = hq < Hh - 1;
    bool wl = wq > 0, wr = wq < Ww - 1;

    if (ht) {
        if (wl) acc += w00 * r0[wq - 1];
        acc += w01 * r0[wq];
        if (wr) acc += w02 * r0[wq + 1];
    }
    {
        if (wl) acc += w10 * r1[wq - 1];
        acc += w11 * r1[wq];
        if (wr) acc += w12 * r1[wq + 1];
    }
    if (hb) {
        if (wl) acc += w20 * r2[wq - 1];
        acc += w21 * r2[wq];
        if (wr) acc += w22 * r2[wq + 1];
    }
    out[(long)c * HW + hq * Ww + wq] = acc;
}

// ---------------- LN stats + apply + split, one batch ----------------
__global__ void stats_kernel(const float* __restrict__ t,
                             const float* __restrict__ lw, const float* __restrict__ lb,
                             __nv_bfloat16* __restrict__ oh, __nv_bfloat16* __restrict__ ol,
                             int npix)
{
    int pix = blockIdx.x * blockDim.x + threadIdx.x;
    if (pix >= npix) return;
    const float* base = t + pix;
    float s = 0.f, s2 = 0.f;
#pragma unroll 8
    for (int c = 0; c < Cc; c++) {
        float v = base[(long)c * HW];
        s += v; s2 += v * v;
    }
    float m = s * (1.0f / Cc);
    float var = s2 * (1.0f / Cc) - m * m;
    float inv = rsqrtf(var + 1e-6f);

    __nv_bfloat16* po = oh + pix;
    __nv_bfloat16* pl = ol + pix;
#pragma unroll 4
    for (int c = 0; c < Cc; c++) {
        float v = (base[(long)c * HW] - m) * inv * lw[c] + lb[c];
        __nv_bfloat16 h, l;
        split_bf16(v, h, l);
        po[(long)c * HW] = h;
        pl[(long)c * HW] = l;
    }
}

// ---------------- elementwise split f32 -> bf16 hi/lo ----------------
__global__ void split_k(const float* __restrict__ src,
                        __nv_bfloat16* __restrict__ hi, __nv_bfloat16* __restrict__ lo,
                        int n4)
{
    int i = blockIdx.x * blockDim.x + threadIdx.x;
    if (i >= n4) return;
    float4 v = ((const float4*)src)[i];
    __nv_bfloat16 h0,l0,h1,l1,h2,l2,h3,l3;
    split_bf16(v.x,h0,l0); split_bf16(v.y,h1,l1);
    split_bf16(v.z,h2,l2); split_bf16(v.w,h3,l3);
    ((uint32_t*)hi)[i*2]   = pk2(h0,h1);
    ((uint32_t*)hi)[i*2+1] = pk2(h2,h3);
    ((uint32_t*)lo)[i*2]   = pk2(l0,l1);
    ((uint32_t*)lo)[i*2+1] = pk2(l2,l3);
}

// ---------------- transpose + split ----------------
__global__ void splitT_k(const float* __restrict__ X,
                         __nv_bfloat16* __restrict__ Oh, __nv_bfloat16* __restrict__ Ol,
                         int Krows, int Ncols)
{
    __shared__ float ts[32][33];
    int n0 = blockIdx.x * 32, k0 = blockIdx.y * 32;
    int tx = threadIdx.x, ty = threadIdx.y;

#pragma unroll
    for (int j = 0; j < 4; j++)
        ts[ty + j*8][tx] = X[(long)(k0 + ty + j*8) * Ncols + n0 + tx];
    __syncthreads();

#pragma unroll
    for (int j = 0; j < 4; j++) {
        int n = n0 + ty + j*8;
        int k = k0 + tx;
        float v = ts[tx][ty + j*8];
        __nv_bfloat16 h, l;
        split_bf16(v, h, l);
        Oh[(long)n * Krows + k] = h;
        Ol[(long)n * Krows + k] = l;
    }
}

// ---------------- bf16 tensor-core GEMM, pre-split streaming ----------------
template<int ACT, int BIASM, bool RES, bool OUTF, bool OUTS>
__global__ void __launch_bounds__(256, 2)
gemm_ps(const __nv_bfloat16* __restrict__ Ah_g, const __nv_bfloat16* __restrict__ Al_g,
        const __nv_bfloat16* __restrict__ Bh_g, const __nv_bfloat16* __restrict__ Bl_g,
        const float* __restrict__ bias, const float* __restrict__ resid,
        float* __restrict__ C, __nv_bfloat16* __restrict__ Oh, __nv_bfloat16* __restrict__ Ol,
        int M, int N, int K, long sA, long sB, long sC)
{
    extern __shared__ __align__(16) char dsm[];
    uint32_t sb = su32(dsm);

    int z = blockIdx.z;
    Ah_g += z * sA; Al_g += z * sA;
    Bh_g += z * sB; Bl_g += z * sB;
    if (OUTF) C += z * sC;
    if (OUTS) { Oh += z * sC; Ol += z * sC; }
    const float* R = RES ? (resid + z * sC) : nullptr;

    int m0 = blockIdx.y * 128;
    int n0 = blockIdx.x * 64;
    int tid = threadIdx.x;
    int warp = tid >> 5;
    int lane = tid & 31;
    int wm = warp & 3;
    int wn = warp >> 2;

    int a_r = tid >> 1;
    int a_c = (tid & 1) * 2;
    int b_r = tid >> 3;
    int b_c = tid & 7;

    const int KT = K >> 5;

    auto loadStage = [&](int st, int kb) {
        uint32_t abase = sb + st * STG_SZ;
        bool mok = (m0 + a_r) < M;
        int ab = mok ? 16 : 0;
        const __nv_bfloat16* sh = Ah_g + (long)(m0 + a_r) * K + kb;
        const __nv_bfloat16* sl = Al_g + (long)(m0 + a_r) * K + kb;
        uint32_t dA = abase + a_r * 80 + a_c * 16;
#pragma unroll
        for (int j = 0; j < 2; j++) {
            cpa16(dA + STG_A_H + j * 16, sh + (a_c + j) * 8, ab);
            cpa16(dA + STG_A_L + j * 16, sl + (a_c + j) * 8, ab);
        }
        const __nv_bfloat16* bh = Bh_g + (long)(kb + b_r) * N + n0 + b_c * 8;
        const __nv_bfloat16* bl = Bl_g + (long)(kb + b_r) * N + n0 + b_c * 8;
        uint32_t dB = abase + b_r * 144 + b_c * 16;
        cpa16(dB + STG_B_H, bh, 16);
        cpa16(dB + STG_B_L, bl, 16);
    };

    loadStage(0, 0);
    CP_COMMIT;
    if (KT > 1) loadStage(1, 32);
    CP_COMMIT;

    float acc[2][4][4];
#pragma unroll
    for (int i = 0; i < 2; i++)
#pragma unroll
        for (int j = 0; j < 4; j++)
#pragma unroll
            for (int q = 0; q < 4; q++) acc[i][j][q] = 0.f;

    int a_mrow = lane & 15;
    int a_kh = (lane >> 4) * 8;
    int bg = lane >> 3;
    int b_kr = (bg & 1) * 8 + (lane & 7);
    int b_nc = (bg >> 1) * 8;

    int st = 0;
    for (int kt = 0; kt < KT; kt++) {
        CP_WAIT1;
        __syncthreads();
        if (kt + 2 < KT) loadStage((st + 2 >= 3) ? st - 1 : st + 2, (kt + 2) << 5);
        CP_COMMIT;

        uint32_t base = sb + st * STG_SZ;
#pragma unroll
        for (int half = 0; half < 2; half++) {
            int kc = half * 16;
            uint32_t afr[2][2][4];
#pragma unroll
            for (int s = 0; s < 2; s++) {
                uint32_t ap = base + (s ? STG_A_L : STG_A_H);
#pragma unroll
                for (int mt = 0; mt < 2; mt++)
                    ldsm4(afr[s][mt], ap + ((wm*32 + mt*16 + a_mrow) * RS + kc + a_kh) * 2);
            }
            uint32_t bfr[2][2][4];
#pragma unroll
            for (int p = 0; p < 2; p++) {
                uint32_t boff = ((kc + b_kr) * RSB + wn*32 + p*16 + b_nc) * 2;
                ldsm4t(bfr[p][0], base + STG_B_H + boff);
                ldsm4t(bfr[p][1], base + STG_B_L + boff);
            }
#pragma unroll
            for (int p = 0; p < 2; p++)
#pragma unroll
                for (int mt = 0; mt < 2; mt++) {
                    mma16816(acc[mt][2*p],   afr[0][mt], bfr[p][0]);
                    mma16816(acc[mt][2*p+1], afr[0][mt], bfr[p][0] + 2);
                }
#pragma unroll
            for (int p = 0; p < 2; p++)
#pragma unroll
                for (int mt = 0; mt < 2; mt++) {
                    mma16816(acc[mt][2*p],   afr[0][mt], bfr[p][1]);
                    mma16816(acc[mt][2*p+1], afr[0][mt], bfr[p][1] + 2);
                }
#pragma unroll
            for (int p = 0; p < 2; p++)
#pragma unroll
                for (int mt = 0; mt < 2; mt++) {
                    mma16816(acc[mt][2*p],   afr[1][mt], bfr[p][0]);
                    mma16816(acc[mt][2*p+1], afr[1][mt], bfr[p][0] + 2);
                }
        }
        st++;
        if (st == 3) st = 0;
    }

    // ---- epilogue ----
#pragma unroll
    for (int mt = 0; mt < 2; mt++) {
#pragma unroll
        for (int nt = 0; nt < 4; nt++) {
            int gn = n0 + wn*32 + nt*8 + (lane & 3) * 2;
            float bn0v = 0.f, bn1v = 0.f;
            if (BIASM == 2) { bn0v = bias[gn]; bn1v = bias[gn + 1]; }
#pragma unroll
            for (int h = 0; h < 2; h++) {
                int row = m0 + wm*32 + mt*16 + (lane >> 2) + h*8;
                if (row >= M) continue;
                float x0 = acc[mt][nt][h*2 + 0];
                float x1 = acc[mt][nt][h*2 + 1];
                if (BIASM == 1) { float bm = bias[row]; x0 += bm; x1 += bm; }
                if (BIASM == 2) { x0 += bn0v; x1 += bn1v; }
                if (ACT == 1) { x0 = fmaxf(x0, 0.f); x1 = fmaxf(x1, 0.f); }
                if (ACT == 2) { x0 = gelu_f(x0); x1 = gelu_f(x1); }
                if (RES) {
                    float2 r2 = *(const float2*)&R[(long)row * N + gn];
                    x0 += r2.x; x1 += r2.y;
                }
                if (OUTF) {
                    float2 o; o.x = x0; o.y = x1;
                    *(float2*)&C[(long)row * N + gn] = o;
                }
                if (OUTS) {
                    __nv_bfloat16 h0, l0, h1, l1;
                    split_bf16(x0, h0, l0);
                    split_bf16(x1, h1, l1);
                    *(uint32_t*)&Oh[(long)row * N + gn] = pk2(h0, h1);
                    *(uint32_t*)&Ol[(long)row * N + gn] = pk2(l0, l1);
                }
            }
        }
    }
}

// ---------------- per-query offset ----------------
__global__ void off_kernel(const float* __restrict__ q4, const float* __restrict__ sb,
                           const float* __restrict__ hb, float* __restrict__ off)
{
    int n = blockIdx.x * blockDim.x + threadIdx.x;
    if (n >= Bb*Nq) return;
    float s = hb[0];
#pragma unroll 8
    for (int i = 0; i < IDim; i++) s += q4[(long)n * IDim + i] * sb[i];
    off[n] = s;
}

// ---------------- bilinear 2x upsample + offset, one batch ----------------
__global__ void upsample_kernel(const float* __restrict__ m, const float* __restrict__ off,
                                float* __restrict__ out)
{
    long idx = (long)blockIdx.x * blockDim.x + threadIdx.x;
    const long tot4 = (long)Nq * H2 * (W2 / 4);
    if (idx >= tot4) return;
    int wq4 = (int)(idx % (W2 / 4)) * 4;
    int h2 = (int)((idx / (W2 / 4)) % H2);
    long bn = idx / ((long)(W2 / 4) * H2);

    float fh = h2 * 0.5f - 0.25f;
    int h0f = (int)floorf(fh);
    float wh = fh - (float)h0f;
    int h0 = max(h0f, 0), h1 = min(h0f + 1, Hh - 1);

    const float* r0 = m + bn * (long)HW + h0 * Ww;
    const float* r1 = m + bn * (long)HW + h1 * Ww;
    float o = off[bn];

    float r[4];
#pragma unroll
    for (int j = 0; j < 4; j++) {
        int w2 = wq4 + j;
        float fw = w2 * 0.5f - 0.25f;
        int w0f = (int)floorf(fw);
        float ww = fw - (float)w0f;
        int w0 = max(w0f, 0), w1 = min(w0f + 1, Ww - 1);
        float t0 = r0[w0] * (1.f - ww) + r0[w1] * ww;
        float t1 = r1[w0] * (1.f - ww) + r1[w1] * ww;
        r[j] = t0 * (1.f - wh) + t1 * wh + o;
    }
    float4 v = make_float4(r[0], r[1], r[2], r[3]);
    *(float4*)(out + bn * (long)(H2 * W2) + (long)h2 * W2 + wq4) = v;
}

// ---------------- launcher ----------------
extern "C" void kernel_launch(void* const* d_in, const int* in_sizes, int n_in,
                              void* d_out, int out_size)
{
    const float* spat    = (const float*)d_in[0];
    const float* qf      = (const float*)d_in[1];
    const float* dw_w    = (const float*)d_in[2];
    const float* dw_b    = (const float*)d_in[3];
    const float* ln_w    = (const float*)d_in[4];
    const float* ln_b    = (const float*)d_in[5];
    const float* pw_w    = (const float*)d_in[6];
    const float* pw_b    = (const float*)d_in[7];
    const float* sproj_w = (const float*)d_in[8];
    const float* sproj_b = (const float*)d_in[9];
    const float* mlp_w1  = (const float*)d_in[10];
    const float* mlp_b1  = (const float*)d_in[11];
    const float* mlp_w2  = (const float*)d_in[12];
    const float* mlp_b2  = (const float*)d_in[13];
    const float* mlp_w3  = (const float*)d_in[14];
    const float* mlp_b3  = (const float*)d_in[15];
    const float* qproj_w = (const float*)d_in[16];
    const float* qproj_b = (const float*)d_in[17];
    const float* head_b  = (const float*)d_in[18];
    float* out = (float*)d_out;

    float *px, *pt, *pq4, *poff, *pm;
    cudaGetSymbolAddress((void**)&px,   g_x);
    cudaGetSymbolAddress((void**)&pt,   g_t);
    cudaGetSymbolAddress((void**)&pq4,  g_q4);
    cudaGetSymbolAddress((void**)&poff, g_off);
    cudaGetSymbolAddress((void**)&pm,   g_m);

    __nv_bfloat16 *pwh,*pwl,*w1h,*w1l,*w2h,*w2l,*w3h,*w3l,*qph,*qpl,*sph,*spl;
    __nv_bfloat16 *qfh,*qfl,*o1h,*o1l,*o2h,*o2l,*o3h,*o3l,*o4h,*o4l,*qqh,*qql,*bsh,*bsl,*ysh,*ysl;
    cudaGetSymbolAddress((void**)&pwh, g_pwh); cudaGetSymbolAddress((void**)&pwl, g_pwl);
    cudaGetSymbolAddress((void**)&w1h, g_w1h); cudaGetSymbolAddress((void**)&w1l, g_w1l);
    cudaGetSymbolAddress((void**)&w2h, g_w2h); cudaGetSymbolAddress((void**)&w2l, g_w2l);
    cudaGetSymbolAddress((void**)&w3h, g_w3h); cudaGetSymbolAddress((void**)&w3l, g_w3l);
    cudaGetSymbolAddress((void**)&qph, g_qph); cudaGetSymbolAddress((void**)&qpl, g_qpl);
    cudaGetSymbolAddress((void**)&sph, g_sph); cudaGetSymbolAddress((void**)&spl, g_spl);
    cudaGetSymbolAddress((void**)&qfh, g_qfh); cudaGetSymbolAddress((void**)&qfl, g_qfl);
    cudaGetSymbolAddress((void**)&o1h, g_o1h); cudaGetSymbolAddress((void**)&o1l, g_o1l);
    cudaGetSymbolAddress((void**)&o2h, g_o2h); cudaGetSymbolAddress((void**)&o2l, g_o2l);
    cudaGetSymbolAddress((void**)&o3h, g_o3h); cudaGetSymbolAddress((void**)&o3l, g_o3l);
    cudaGetSymbolAddress((void**)&o4h, g_o4h); cudaGetSymbolAddress((void**)&o4l, g_o4l);
    cudaGetSymbolAddress((void**)&qqh, g_qqh); cudaGetSymbolAddress((void**)&qql, g_qql);
    cudaGetSymbolAddress((void**)&bsh, g_bsh); cudaGetSymbolAddress((void**)&bsl, g_bsl);
    cudaGetSymbolAddress((void**)&ysh, g_ysh); cudaGetSymbolAddress((void**)&ysl, g_ysl);

    cudaFuncSetAttribute(gemm_ps<1,2,false,false,true>,  cudaFuncAttributeMaxDynamicSharedMemorySize, SMEMB);
    cudaFuncSetAttribute(gemm_ps<2,1,true,true,false>,   cudaFuncAttributeMaxDynamicSharedMemorySize, SMEMB);
    cudaFuncSetAttribute(gemm_ps<2,1,true,false,true>,   cudaFuncAttributeMaxDynamicSharedMemorySize, SMEMB);
    cudaFuncSetAttribute(gemm_ps<0,2,false,false,true>,  cudaFuncAttributeMaxDynamicSharedMemorySize, SMEMB);
    cudaFuncSetAttribute(gemm_ps<0,2,false,true,true>,   cudaFuncAttributeMaxDynamicSharedMemorySize, SMEMB);
    cudaFuncSetAttribute(gemm_ps<0,0,false,false,true>,  cudaFuncAttributeMaxDynamicSharedMemorySize, SMEMB);
    cudaFuncSetAttribute(gemm_ps<0,0,false,true,false>,  cudaFuncAttributeMaxDynamicSharedMemorySize, SMEMB);

    dim3 dwBlock(80, 4);
    dim3 dwGrid(1, Hh / 4, Cc);
    dim3 tBlock(32, 8);
    const int Mq = Bb * Nq;
    const long NHW = (long)Nq * HW;
    const long NH2W2 = (long)Nq * H2 * W2;

    // ---- streams & events: created EXACTLY ONCE, minimal footprint
    // (2 extra streams / 3 events — the 4-stream variant left a 2MB driver
    //  pool live after graph teardown and tripped the guard).
    static bool s_init = false;
    static cudaStream_t sq, sb;
    static cudaEvent_t evFork, evQ, evB;
    if (!s_init) {
        cudaStreamCreateWithFlags(&sq, cudaStreamNonBlocking);
        cudaStreamCreateWithFlags(&sb, cudaStreamNonBlocking);
        cudaEventCreateWithFlags(&evFork, cudaEventDisableTiming);
        cudaEventCreateWithFlags(&evQ,    cudaEventDisableTiming);
        cudaEventCreateWithFlags(&evB,    cudaEventDisableTiming);
        s_init = true;
    }

    // ---- stream 0: pw weight split first (both spatial chains need it) ----
    split_k<<<(2*Cc*Cc/4 + 255)/256, 256>>>(pw_w, pwh, pwl, 2*Cc*Cc/4);
    cudaEventRecord(evFork, 0);
    cudaStreamWaitEvent(sq, evFork, 0);
    cudaStreamWaitEvent(sb, evFork, 0);

    // ======== query stream: full query chain ========
    split_k<<<(Mq*Cc/4 + 255)/256, 256, 0, sq>>>(qf, qfh, qfl, Mq*Cc/4);
    splitT_k<<<dim3(Cc/32, HID/32, 1), tBlock, 0, sq>>>(mlp_w1, w1h, w1l, HID, Cc);
    splitT_k<<<dim3(HID/32, HID/32, 1), tBlock, 0, sq>>>(mlp_w2, w2h, w2l, HID, HID);
    splitT_k<<<dim3(HID/32, Cc/32, 1), tBlock, 0, sq>>>(mlp_w3, w3h, w3l, Cc, HID);
    splitT_k<<<dim3(Cc/32, IDim/32, 1), tBlock, 0, sq>>>(qproj_w, qph, qpl, IDim, Cc);
    split_k<<<(IDim*Cc/4 + 255)/256, 256, 0, sq>>>(sproj_w, sph, spl, IDim*Cc/4);

    gemm_ps<1, 2, false, false, true><<<dim3(HID/64, 10, 1), 256, SMEMB, sq>>>(
        qfh, qfl, w1h, w1l, mlp_b1, nullptr, nullptr, o1h, o1l,
        Mq, HID, Cc, 0, 0, 0);
    gemm_ps<1, 2, false, false, true><<<dim3(HID/64, 10, 1), 256, SMEMB, sq>>>(
        o1h, o1l, w2h, w2l, mlp_b2, nullptr, nullptr, o2h, o2l,
        Mq, HID, HID, 0, 0, 0);
    gemm_ps<0, 2, false, false, true><<<dim3(Cc/64, 10, 1), 256, SMEMB, sq>>>(
        o2h, o2l, w3h, w3l, mlp_b3, nullptr, nullptr, o3h, o3l,
        Mq, Cc, HID, 0, 0, 0);
    gemm_ps<0, 2, false, true, true><<<dim3(IDim/64, 10, 1), 256, SMEMB, sq>>>(
        o3h, o3l, qph, qpl, qproj_b, nullptr, pq4, o4h, o4l,
        Mq, IDim, Cc, 0, 0, 0);
    gemm_ps<0, 0, false, false, true><<<dim3(Cc/64, 10, 1), 256, SMEMB, sq>>>(
        o4h, o4l, sph, spl, nullptr, nullptr, nullptr, qqh, qql,
        Mq, Cc, IDim, 0, 0, 0);
    off_kernel<<<(Mq + 255)/256, 256, 0, sq>>>(pq4, sproj_b, head_b, poff);
    cudaEventRecord(evQ, sq);

    // ======== spatial chains: batches {0,1} on stream 0, {2,3} on sb ========
    for (int b = 0; b < Bb; b++) {
        cudaStream_t st = (b < 2) ? (cudaStream_t)0 : sb;
        long co = (long)b * CHW;
        // block 0
        dw_kernel<<<dwGrid, dwBlock, 0, st>>>(spat + co, dw_w, dw_b, pt + co);
        stats_kernel<<<(HW + 255)/256, 256, 0, st>>>(pt + co, ln_w, ln_b, bsh + co, bsl + co, HW);
        gemm_ps<2, 1, true, true, false><<<dim3(HW/64, 2, 1), 256, SMEMB, st>>>(
            pwh, pwl, bsh + co, bsl + co, pw_b, spat + co, px + co, nullptr, nullptr,
            Cc, HW, Cc, 0, 0, 0);
        // block 1
        dw_kernel<<<dwGrid, dwBlock, 0, st>>>(px + co, dw_w + Cc*9, dw_b + Cc, pt + co);
        stats_kernel<<<(HW + 255)/256, 256, 0, st>>>(pt + co, ln_w + Cc, ln_b + Cc, bsh + co, bsl + co, HW);
        gemm_ps<2, 1, true, false, true><<<dim3(HW/64, 2, 1), 256, SMEMB, st>>>(
            pwh + Cc*Cc, pwl + Cc*Cc, bsh + co, bsl + co, pw_b + Cc, px + co, nullptr, ysh + co, ysl + co,
            Cc, HW, Cc, 0, 0, 0);
        // mask + upsample for this batch (needs query chain)
        cudaStreamWaitEvent(st, evQ, 0);
        gemm_ps<0, 0, false, true, false><<<dim3(HW/64, 3, 1), 256, SMEMB, st>>>(
            qqh + (long)b*Nq*Cc, qql + (long)b*Nq*Cc, ysh + co, ysl + co,
            nullptr, nullptr, pm + (long)b*NHW, nullptr, nullptr,
            Nq, HW, Cc, 0, 0, 0);
        const long tot4 = NH2W2 / 4;
        upsample_kernel<<<(unsigned)((tot4 + 255)/256), 256, 0, st>>>(
            pm + (long)b*NHW, poff + (long)b*Nq, out + (long)b*NH2W2);
    }
    cudaEventRecord(evB, sb);

    // ---- join: stream 0 waits for sb ----
    cudaStreamWaitEvent(0, evB, 0);
}

// round 16
// speedup vs baseline: 1.1695x; 1.1695x over previous
#include <cuda_runtime.h>
#include <cuda_bf16.h>
#include <math.h>
#include <stdint.h>
#include <string.h>

// ---------------- problem constants ----------------
#define Bb 4
#define Cc 256
#define Hh 80
#define Ww 80
#define Nq 300
#define IDim 128
#define HID 512
#define H2 160
#define W2 160
#define HW (Hh*Ww)
#define CHW (Cc*HW)

// ---------------- GEMM tile geometry ----------------
#define RS 40
#define RSB 72
#define STG_A_H 0
#define STG_A_L 10240
#define STG_B_H 20480
#define STG_B_L 25088
#define STG_SZ 29696
#define SMEMB (3*STG_SZ)

// ---------------- device scratch (f32) ----------------
__device__ float g_x[Bb*CHW];
__device__ float g_t[Bb*CHW];
__device__ float g_q4[Bb*Nq*IDim];
__device__ float g_off[Bb*Nq];
__device__ float g_m[Bb*Nq*HW];

// ---------------- device scratch (bf16 hi/lo planes) ----------------
__device__ __nv_bfloat16 g_pwh[2*Cc*Cc],  g_pwl[2*Cc*Cc];
__device__ __nv_bfloat16 g_w1h[Cc*HID],   g_w1l[Cc*HID];
__device__ __nv_bfloat16 g_w2h[HID*HID],  g_w2l[HID*HID];
__device__ __nv_bfloat16 g_w3h[HID*Cc],   g_w3l[HID*Cc];
__device__ __nv_bfloat16 g_qph[Cc*IDim],  g_qpl[Cc*IDim];
__device__ __nv_bfloat16 g_sph[IDim*Cc],  g_spl[IDim*Cc];
__device__ __nv_bfloat16 g_qfh[Bb*Nq*Cc], g_qfl[Bb*Nq*Cc];
__device__ __nv_bfloat16 g_o1h[Bb*Nq*HID],g_o1l[Bb*Nq*HID];
__device__ __nv_bfloat16 g_o2h[Bb*Nq*HID],g_o2l[Bb*Nq*HID];
__device__ __nv_bfloat16 g_o3h[Bb*Nq*Cc], g_o3l[Bb*Nq*Cc];
__device__ __nv_bfloat16 g_o4h[Bb*Nq*IDim],g_o4l[Bb*Nq*IDim];
__device__ __nv_bfloat16 g_qqh[Bb*Nq*Cc], g_qql[Bb*Nq*Cc];
__device__ __nv_bfloat16 g_bsh[Bb*CHW],   g_bsl[Bb*CHW];
__device__ __nv_bfloat16 g_ysh[Bb*CHW],   g_ysl[Bb*CHW];

__device__ __forceinline__ float gelu_f(float x) {
    return 0.5f * x * (1.0f + erff(x * 0.70710678118654752f));
}
__device__ __forceinline__ uint32_t su32(const void* p) {
    return (uint32_t)__cvta_generic_to_shared(p);
}
__device__ __forceinline__ void ldsm4(uint32_t* r, uint32_t addr) {
    asm volatile("ldmatrix.sync.aligned.m8n8.x4.shared.b16 {%0,%1,%2,%3}, [%4];"
        : "=r"(r[0]), "=r"(r[1]), "=r"(r[2]), "=r"(r[3]) : "r"(addr));
}
__device__ __forceinline__ void ldsm4t(uint32_t* r, uint32_t addr) {
    asm volatile("ldmatrix.sync.aligned.m8n8.x4.trans.shared.b16 {%0,%1,%2,%3}, [%4];"
        : "=r"(r[0]), "=r"(r[1]), "=r"(r[2]), "=r"(r[3]) : "r"(addr));
}
__device__ __forceinline__ void mma16816(float* d, const uint32_t* a, const uint32_t* b) {
    asm volatile("mma.sync.aligned.m16n8k16.row.col.f32.bf16.bf16.f32 "
        "{%0,%1,%2,%3}, {%4,%5,%6,%7}, {%8,%9}, {%0,%1,%2,%3};"
        : "+f"(d[0]), "+f"(d[1]), "+f"(d[2]), "+f"(d[3])
        : "r"(a[0]), "r"(a[1]), "r"(a[2]), "r"(a[3]), "r"(b[0]), "r"(b[1]));
}
__device__ __forceinline__ void split_bf16(float x, __nv_bfloat16& hi, __nv_bfloat16& lo) {
    hi = __float2bfloat16(x);
    lo = __float2bfloat16(x - __bfloat162float(hi));
}
__device__ __forceinline__ uint32_t pk2(__nv_bfloat16 a, __nv_bfloat16 b) {
    __nv_bfloat162 t(a, b);
    uint32_t u;
    memcpy(&u, &t, 4);
    return u;
}
__device__ __forceinline__ void cpa16(uint32_t d, const void* s, int bytes) {
    asm volatile("cp.async.cg.shared.global [%0], [%1], 16, %2;"
        :: "r"(d), "l"(s), "r"(bytes));
}
#define CP_COMMIT asm volatile("cp.async.commit_group;")
#define CP_WAIT1  asm volatile("cp.async.wait_group 1;")

// ---------------- depthwise 3x3 conv, nb batches (gridDim.z = nb*Cc) ----------------
__global__ void dw_kernel(const float* __restrict__ x, const float* __restrict__ w,
                          const float* __restrict__ bia, float* __restrict__ out)
{
    int wq = threadIdx.x;
    int hq = blockIdx.y * 4 + threadIdx.y;
    int plane = blockIdx.z;
    int c = plane & (Cc - 1);
    const float* xp = x + (long)plane * HW;
    const float* wp = w + c * 9;
    float w00 = wp[0], w01 = wp[1], w02 = wp[2];
    float w10 = wp[3], w11 = wp[4], w12 = wp[5];
    float w20 = wp[6], w21 = wp[7], w22 = wp[8];
    float acc = bia[c];

    const float* r0 = xp + (hq - 1) * Ww;
    const float* r1 = xp + hq * Ww;
    const float* r2 = xp + (hq + 1) * Ww;
    bool ht = hq > 0, hb = hq < Hh - 1;
    bool wl = wq > 0, wr = wq < Ww - 1;

    if (ht) {
        if (wl) acc += w00 * r0[wq - 1];
        acc += w01 * r0[wq];
        if (wr) acc += w02 * r0[wq + 1];
    }
    {
        if (wl) acc += w10 * r1[wq - 1];
        acc += w11 * r1[wq];
        if (wr) acc += w12 * r1[wq + 1];
    }
    if (hb) {
        if (wl) acc += w20 * r2[wq - 1];
        acc += w21 * r2[wq];
        if (wr) acc += w22 * r2[wq + 1];
    }
    out[(long)plane * HW + hq * Ww + wq] = acc;
}

// ---------------- LN stats + apply + split, nb batches ----------------
__global__ void stats_kernel(const float* __restrict__ t,
                             const float* __restrict__ lw, const float* __restrict__ lb,
                             __nv_bfloat16* __restrict__ oh, __nv_bfloat16* __restrict__ ol,
                             int npix)
{
    int p = blockIdx.x * blockDim.x + threadIdx.x;
    if (p >= npix) return;
    int bb = p / HW;
    int pix = p - bb * HW;
    const float* base = t + (long)bb * CHW + pix;
    float s = 0.f, s2 = 0.f;
#pragma unroll 8
    for (int c = 0; c < Cc; c++) {
        float v = base[(long)c * HW];
        s += v; s2 += v * v;
    }
    float m = s * (1.0f / Cc);
    float var = s2 * (1.0f / Cc) - m * m;
    float inv = rsqrtf(var + 1e-6f);

    __nv_bfloat16* po = oh + (long)bb * CHW + pix;
    __nv_bfloat16* pl = ol + (long)bb * CHW + pix;
#pragma unroll 4
    for (int c = 0; c < Cc; c++) {
        float v = (base[(long)c * HW] - m) * inv * lw[c] + lb[c];
        __nv_bfloat16 h, l;
        split_bf16(v, h, l);
        po[(long)c * HW] = h;
        pl[(long)c * HW] = l;
    }
}

// ---------------- elementwise split f32 -> bf16 hi/lo ----------------
__global__ void split_k(const float* __restrict__ src,
                        __nv_bfloat16* __restrict__ hi, __nv_bfloat16* __restrict__ lo,
                        int n4)
{
    int i = blockIdx.x * blockDim.x + threadIdx.x;
    if (i >= n4) return;
    float4 v = ((const float4*)src)[i];
    __nv_bfloat16 h0,l0,h1,l1,h2,l2,h3,l3;
    split_bf16(v.x,h0,l0); split_bf16(v.y,h1,l1);
    split_bf16(v.z,h2,l2); split_bf16(v.w,h3,l3);
    ((uint32_t*)hi)[i*2]   = pk2(h0,h1);
    ((uint32_t*)hi)[i*2+1] = pk2(h2,h3);
    ((uint32_t*)lo)[i*2]   = pk2(l0,l1);
    ((uint32_t*)lo)[i*2+1] = pk2(l2,l3);
}

// ---------------- transpose + split ----------------
__global__ void splitT_k(const float* __restrict__ X,
                         __nv_bfloat16* __restrict__ Oh, __nv_bfloat16* __restrict__ Ol,
                         int Krows, int Ncols)
{
    __shared__ float ts[32][33];
    int n0 = blockIdx.x * 32, k0 = blockIdx.y * 32;
    int tx = threadIdx.x, ty = threadIdx.y;

#pragma unroll
    for (int j = 0; j < 4; j++)
        ts[ty + j*8][tx] = X[(long)(k0 + ty + j*8) * Ncols + n0 + tx];
    __syncthreads();

#pragma unroll
    for (int j = 0; j < 4; j++) {
        int n = n0 + ty + j*8;
        int k = k0 + tx;
        float v = ts[tx][ty + j*8];
        __nv_bfloat16 h, l;
        split_bf16(v, h, l);
        Oh[(long)n * Krows + k] = h;
        Ol[(long)n * Krows + k] = l;
    }
}

// ---------------- bf16 tensor-core GEMM, pre-split streaming ----------------
template<int ACT, int BIASM, bool RES, bool OUTF, bool OUTS>
__global__ void __launch_bounds__(256, 2)
gemm_ps(const __nv_bfloat16* __restrict__ Ah_g, const __nv_bfloat16* __restrict__ Al_g,
        const __nv_bfloat16* __restrict__ Bh_g, const __nv_bfloat16* __restrict__ Bl_g,
        const float* __restrict__ bias, const float* __restrict__ resid,
        float* __restrict__ C, __nv_bfloat16* __restrict__ Oh, __nv_bfloat16* __restrict__ Ol,
        int M, int N, int K, long sA, long sB, long sC)
{
    extern __shared__ __align__(16) char dsm[];
    uint32_t sb = su32(dsm);

    int z = blockIdx.z;
    Ah_g += z * sA; Al_g += z * sA;
    Bh_g += z * sB; Bl_g += z * sB;
    if (OUTF) C += z * sC;
    if (OUTS) { Oh += z * sC; Ol += z * sC; }
    const float* R = RES ? (resid + z * sC) : nullptr;

    int m0 = blockIdx.y * 128;
    int n0 = blockIdx.x * 64;
    int tid = threadIdx.x;
    int warp = tid >> 5;
    int lane = tid & 31;
    int wm = warp & 3;
    int wn = warp >> 2;

    int a_r = tid >> 1;
    int a_c = (tid & 1) * 2;
    int b_r = tid >> 3;
    int b_c = tid & 7;

    const int KT = K >> 5;

    auto loadStage = [&](int st, int kb) {
        uint32_t abase = sb + st * STG_SZ;
        bool mok = (m0 + a_r) < M;
        int ab = mok ? 16 : 0;
        const __nv_bfloat16* sh = Ah_g + (long)(m0 + a_r) * K + kb;
        const __nv_bfloat16* sl = Al_g + (long)(m0 + a_r) * K + kb;
        uint32_t dA = abase + a_r * 80 + a_c * 16;
#pragma unroll
        for (int j = 0; j < 2; j++) {
            cpa16(dA + STG_A_H + j * 16, sh + (a_c + j) * 8, ab);
            cpa16(dA + STG_A_L + j * 16, sl + (a_c + j) * 8, ab);
        }
        const __nv_bfloat16* bh = Bh_g + (long)(kb + b_r) * N + n0 + b_c * 8;
        const __nv_bfloat16* bl = Bl_g + (long)(kb + b_r) * N + n0 + b_c * 8;
        uint32_t dB = abase + b_r * 144 + b_c * 16;
        cpa16(dB + STG_B_H, bh, 16);
        cpa16(dB + STG_B_L, bl, 16);
    };

    loadStage(0, 0);
    CP_COMMIT;
    if (KT > 1) loadStage(1, 32);
    CP_COMMIT;

    float acc[2][4][4];
#pragma unroll
    for (int i = 0; i < 2; i++)
#pragma unroll
        for (int j = 0; j < 4; j++)
#pragma unroll
            for (int q = 0; q < 4; q++) acc[i][j][q] = 0.f;

    int a_mrow = lane & 15;
    int a_kh = (lane >> 4) * 8;
    int bg = lane >> 3;
    int b_kr = (bg & 1) * 8 + (lane & 7);
    int b_nc = (bg >> 1) * 8;

    int st = 0;
    for (int kt = 0; kt < KT; kt++) {
        CP_WAIT1;
        __syncthreads();
        if (kt + 2 < KT) loadStage((st + 2 >= 3) ? st - 1 : st + 2, (kt + 2) << 5);
        CP_COMMIT;

        uint32_t base = sb + st * STG_SZ;
#pragma unroll
        for (int half = 0; half < 2; half++) {
            int kc = half * 16;
            uint32_t afr[2][2][4];
#pragma unroll
            for (int s = 0; s < 2; s++) {
                uint32_t ap = base + (s ? STG_A_L : STG_A_H);
#pragma unroll
                for (int mt = 0; mt < 2; mt++)
                    ldsm4(afr[s][mt], ap + ((wm*32 + mt*16 + a_mrow) * RS + kc + a_kh) * 2);
            }
            uint32_t bfr[2][2][4];
#pragma unroll
            for (int p = 0; p < 2; p++) {
                uint32_t boff = ((kc + b_kr) * RSB + wn*32 + p*16 + b_nc) * 2;
                ldsm4t(bfr[p][0], base + STG_B_H + boff);
                ldsm4t(bfr[p][1], base + STG_B_L + boff);
            }
#pragma unroll
            for (int p = 0; p < 2; p++)
#pragma unroll
                for (int mt = 0; mt < 2; mt++) {
                    mma16816(acc[mt][2*p],   afr[0][mt], bfr[p][0]);
                    mma16816(acc[mt][2*p+1], afr[0][mt], bfr[p][0] + 2);
                }
#pragma unroll
            for (int p = 0; p < 2; p++)
#pragma unroll
                for (int mt = 0; mt < 2; mt++) {
                    mma16816(acc[mt][2*p],   afr[0][mt], bfr[p][1]);
                    mma16816(acc[mt][2*p+1], afr[0][mt], bfr[p][1] + 2);
                }
#pragma unroll
            for (int p = 0; p < 2; p++)
#pragma unroll
                for (int mt = 0; mt < 2; mt++) {
                    mma16816(acc[mt][2*p],   afr[1][mt], bfr[p][0]);
                    mma16816(acc[mt][2*p+1], afr[1][mt], bfr[p][0] + 2);
                }
        }
        st++;
        if (st == 3) st = 0;
    }

    // ---- epilogue ----
#pragma unroll
    for (int mt = 0; mt < 2; mt++) {
#pragma unroll
        for (int nt = 0; nt < 4; nt++) {
            int gn = n0 + wn*32 + nt*8 + (lane & 3) * 2;
            float bn0v = 0.f, bn1v = 0.f;
            if (BIASM == 2) { bn0v = bias[gn]; bn1v = bias[gn + 1]; }
#pragma unroll
            for (int h = 0; h < 2; h++) {
                int row = m0 + wm*32 + mt*16 + (lane >> 2) + h*8;
                if (row >= M) continue;
                float x0 = acc[mt][nt][h*2 + 0];
                float x1 = acc[mt][nt][h*2 + 1];
                if (BIASM == 1) { float bm = bias[row]; x0 += bm; x1 += bm; }
                if (BIASM == 2) { x0 += bn0v; x1 += bn1v; }
                if (ACT == 1) { x0 = fmaxf(x0, 0.f); x1 = fmaxf(x1, 0.f); }
                if (ACT == 2) { x0 = gelu_f(x0); x1 = gelu_f(x1); }
                if (RES) {
                    float2 r2 = *(const float2*)&R[(long)row * N + gn];
                    x0 += r2.x; x1 += r2.y;
                }
                if (OUTF) {
                    float2 o; o.x = x0; o.y = x1;
                    *(float2*)&C[(long)row * N + gn] = o;
                }
                if (OUTS) {
                    __nv_bfloat16 h0, l0, h1, l1;
                    split_bf16(x0, h0, l0);
                    split_bf16(x1, h1, l1);
                    *(uint32_t*)&Oh[(long)row * N + gn] = pk2(h0, h1);
                    *(uint32_t*)&Ol[(long)row * N + gn] = pk2(l0, l1);
                }
            }
        }
    }
}

// ---------------- per-query offset ----------------
__global__ void off_kernel(const float* __restrict__ q4, const float* __restrict__ sb,
                           const float* __restrict__ hb, float* __restrict__ off)
{
    int n = blockIdx.x * blockDim.x + threadIdx.x;
    if (n >= Bb*Nq) return;
    float s = hb[0];
#pragma unroll 8
    for (int i = 0; i < IDim; i++) s += q4[(long)n * IDim + i] * sb[i];
    off[n] = s;
}

// ---------------- bilinear 2x upsample + offset (nbn = #(b,n) rows) ----------------
__global__ void upsample_kernel(const float* __restrict__ m, const float* __restrict__ off,
                                float* __restrict__ out, int nbn)
{
    long idx = (long)blockIdx.x * blockDim.x + threadIdx.x;
    const long tot4 = (long)nbn * H2 * (W2 / 4);
    if (idx >= tot4) return;
    int wq4 = (int)(idx % (W2 / 4)) * 4;
    int h2 = (int)((idx / (W2 / 4)) % H2);
    long bn = idx / ((long)(W2 / 4) * H2);

    float fh = h2 * 0.5f - 0.25f;
    int h0f = (int)floorf(fh);
    float wh = fh - (float)h0f;
    int h0 = max(h0f, 0), h1 = min(h0f + 1, Hh - 1);

    const float* r0 = m + bn * (long)HW + h0 * Ww;
    const float* r1 = m + bn * (long)HW + h1 * Ww;
    float o = off[bn];

    float r[4];
#pragma unroll
    for (int j = 0; j < 4; j++) {
        int w2 = wq4 + j;
        float fw = w2 * 0.5f - 0.25f;
        int w0f = (int)floorf(fw);
        float ww = fw - (float)w0f;
        int w0 = max(w0f, 0), w1 = min(w0f + 1, Ww - 1);
        float t0 = r0[w0] * (1.f - ww) + r0[w1] * ww;
        float t1 = r1[w0] * (1.f - ww) + r1[w1] * ww;
        r[j] = t0 * (1.f - wh) + t1 * wh + o;
    }
    float4 v = make_float4(r[0], r[1], r[2], r[3]);
    *(float4*)(out + bn * (long)(H2 * W2) + (long)h2 * W2 + wq4) = v;
}

// ---------------- launcher ----------------
extern "C" void kernel_launch(void* const* d_in, const int* in_sizes, int n_in,
                              void* d_out, int out_size)
{
    const float* spat    = (const float*)d_in[0];
    const float* qf      = (const float*)d_in[1];
    const float* dw_w    = (const float*)d_in[2];
    const float* dw_b    = (const float*)d_in[3];
    const float* ln_w    = (const float*)d_in[4];
    const float* ln_b    = (const float*)d_in[5];
    const float* pw_w    = (const float*)d_in[6];
    const float* pw_b    = (const float*)d_in[7];
    const float* sproj_w = (const float*)d_in[8];
    const float* sproj_b = (const float*)d_in[9];
    const float* mlp_w1  = (const float*)d_in[10];
    const float* mlp_b1  = (const float*)d_in[11];
    const float* mlp_w2  = (const float*)d_in[12];
    const float* mlp_b2  = (const float*)d_in[13];
    const float* mlp_w3  = (const float*)d_in[14];
    const float* mlp_b3  = (const float*)d_in[15];
    const float* qproj_w = (const float*)d_in[16];
    const float* qproj_b = (const float*)d_in[17];
    const float* head_b  = (const float*)d_in[18];
    float* out = (float*)d_out;

    float *px, *pt, *pq4, *poff, *pm;
    cudaGetSymbolAddress((void**)&px,   g_x);
    cudaGetSymbolAddress((void**)&pt,   g_t);
    cudaGetSymbolAddress((void**)&pq4,  g_q4);
    cudaGetSymbolAddress((void**)&poff, g_off);
    cudaGetSymbolAddress((void**)&pm,   g_m);

    __nv_bfloat16 *pwh,*pwl,*w1h,*w1l,*w2h,*w2l,*w3h,*w3l,*qph,*qpl,*sph,*spl;
    __nv_bfloat16 *qfh,*qfl,*o1h,*o1l,*o2h,*o2l,*o3h,*o3l,*o4h,*o4l,*qqh,*qql,*bsh,*bsl,*ysh,*ysl;
    cudaGetSymbolAddress((void**)&pwh, g_pwh); cudaGetSymbolAddress((void**)&pwl, g_pwl);
    cudaGetSymbolAddress((void**)&w1h, g_w1h); cudaGetSymbolAddress((void**)&w1l, g_w1l);
    cudaGetSymbolAddress((void**)&w2h, g_w2h); cudaGetSymbolAddress((void**)&w2l, g_w2l);
    cudaGetSymbolAddress((void**)&w3h, g_w3h); cudaGetSymbolAddress((void**)&w3l, g_w3l);
    cudaGetSymbolAddress((void**)&qph, g_qph); cudaGetSymbolAddress((void**)&qpl, g_qpl);
    cudaGetSymbolAddress((void**)&sph, g_sph); cudaGetSymbolAddress((void**)&spl, g_spl);
    cudaGetSymbolAddress((void**)&qfh, g_qfh); cudaGetSymbolAddress((void**)&qfl, g_qfl);
    cudaGetSymbolAddress((void**)&o1h, g_o1h); cudaGetSymbolAddress((void**)&o1l, g_o1l);
    cudaGetSymbolAddress((void**)&o2h, g_o2h); cudaGetSymbolAddress((void**)&o2l, g_o2l);
    cudaGetSymbolAddress((void**)&o3h, g_o3h); cudaGetSymbolAddress((void**)&o3l, g_o3l);
    cudaGetSymbolAddress((void**)&o4h, g_o4h); cudaGetSymbolAddress((void**)&o4l, g_o4l);
    cudaGetSymbolAddress((void**)&qqh, g_qqh); cudaGetSymbolAddress((void**)&qql, g_qql);
    cudaGetSymbolAddress((void**)&bsh, g_bsh); cudaGetSymbolAddress((void**)&bsl, g_bsl);
    cudaGetSymbolAddress((void**)&ysh, g_ysh); cudaGetSymbolAddress((void**)&ysl, g_ysl);

    cudaFuncSetAttribute(gemm_ps<1,2,false,false,true>,  cudaFuncAttributeMaxDynamicSharedMemorySize, SMEMB);
    cudaFuncSetAttribute(gemm_ps<2,1,true,true,false>,   cudaFuncAttributeMaxDynamicSharedMemorySize, SMEMB);
    cudaFuncSetAttribute(gemm_ps<2,1,true,false,true>,   cudaFuncAttributeMaxDynamicSharedMemorySize, SMEMB);
    cudaFuncSetAttribute(gemm_ps<0,2,false,false,true>,  cudaFuncAttributeMaxDynamicSharedMemorySize, SMEMB);
    cudaFuncSetAttribute(gemm_ps<0,2,false,true,true>,   cudaFuncAttributeMaxDynamicSharedMemorySize, SMEMB);
    cudaFuncSetAttribute(gemm_ps<0,0,false,false,true>,  cudaFuncAttributeMaxDynamicSharedMemorySize, SMEMB);
    cudaFuncSetAttribute(gemm_ps<0,0,false,true,false>,  cudaFuncAttributeMaxDynamicSharedMemorySize, SMEMB);

    dim3 dwBlock(80, 4);
    dim3 dwGrid2(1, Hh / 4, 2 * Cc);   // 2 batches per chain
    dim3 tBlock(32, 8);
    const int Mq = Bb * Nq;
    const long NHW = (long)Nq * HW;
    const long NH2W2 = (long)Nq * H2 * W2;

    // ---- streams & events: created EXACTLY ONCE (teardown-safe footprint) ----
    static bool s_init = false;
    static cudaStream_t sq, sb;
    static cudaEvent_t evFork, evQ, evB;
    if (!s_init) {
        cudaStreamCreateWithFlags(&sq, cudaStreamNonBlocking);
        cudaStreamCreateWithFlags(&sb, cudaStreamNonBlocking);
        cudaEventCreateWithFlags(&evFork, cudaEventDisableTiming);
        cudaEventCreateWithFlags(&evQ,    cudaEventDisableTiming);
        cudaEventCreateWithFlags(&evB,    cudaEventDisableTiming);
        s_init = true;
    }

    // ---- stream 0: pw weight split first (both spatial chains need it) ----
    split_k<<<(2*Cc*Cc/4 + 255)/256, 256>>>(pw_w, pwh, pwl, 2*Cc*Cc/4);
    cudaEventRecord(evFork, 0);
    cudaStreamWaitEvent(sq, evFork, 0);
    cudaStreamWaitEvent(sb, evFork, 0);

    // ======== query stream: full query chain ========
    split_k<<<(Mq*Cc/4 + 255)/256, 256, 0, sq>>>(qf, qfh, qfl, Mq*Cc/4);
    splitT_k<<<dim3(Cc/32, HID/32, 1), tBlock, 0, sq>>>(mlp_w1, w1h, w1l, HID, Cc);
    splitT_k<<<dim3(HID/32, HID/32, 1), tBlock, 0, sq>>>(mlp_w2, w2h, w2l, HID, HID);
    splitT_k<<<dim3(HID/32, Cc/32, 1), tBlock, 0, sq>>>(mlp_w3, w3h, w3l, Cc, HID);
    splitT_k<<<dim3(Cc/32, IDim/32, 1), tBlock, 0, sq>>>(qproj_w, qph, qpl, IDim, Cc);
    split_k<<<(IDim*Cc/4 + 255)/256, 256, 0, sq>>>(sproj_w, sph, spl, IDim*Cc/4);

    gemm_ps<1, 2, false, false, true><<<dim3(HID/64, 10, 1), 256, SMEMB, sq>>>(
        qfh, qfl, w1h, w1l, mlp_b1, nullptr, nullptr, o1h, o1l,
        Mq, HID, Cc, 0, 0, 0);
    gemm_ps<1, 2, false, false, true><<<dim3(HID/64, 10, 1), 256, SMEMB, sq>>>(
        o1h, o1l, w2h, w2l, mlp_b2, nullptr, nullptr, o2h, o2l,
        Mq, HID, HID, 0, 0, 0);
    gemm_ps<0, 2, false, false, true><<<dim3(Cc/64, 10, 1), 256, SMEMB, sq>>>(
        o2h, o2l, w3h, w3l, mlp_b3, nullptr, nullptr, o3h, o3l,
        Mq, Cc, HID, 0, 0, 0);
    gemm_ps<0, 2, false, true, true><<<dim3(IDim/64, 10, 1), 256, SMEMB, sq>>>(
        o3h, o3l, qph, qpl, qproj_b, nullptr, pq4, o4h, o4l,
        Mq, IDim, Cc, 0, 0, 0);
    gemm_ps<0, 0, false, false, true><<<dim3(Cc/64, 10, 1), 256, SMEMB, sq>>>(
        o4h, o4l, sph, spl, nullptr, nullptr, nullptr, qqh, qql,
        Mq, Cc, IDim, 0, 0, 0);
    off_kernel<<<(Mq + 255)/256, 256, 0, sq>>>(pq4, sproj_b, head_b, poff);
    cudaEventRecord(evQ, sq);

    // ======== half-batch spatial chains (z=2): {0,1} on stream 0, {2,3} on sb ========
    for (int g = 0; g < 2; g++) {
        cudaStream_t st = (g == 0) ? (cudaStream_t)0 : sb;
        int b0 = g * 2;
        long co = (long)b0 * CHW;
        // block 0 (2 batches)
        dw_kernel<<<dwGrid2, dwBlock, 0, st>>>(spat + co, dw_w, dw_b, pt + co);
        stats_kernel<<<(2*HW + 255)/256, 256, 0, st>>>(pt + co, ln_w, ln_b, bsh + co, bsl + co, 2*HW);
        gemm_ps<2, 1, true, true, false><<<dim3(HW/64, 2, 2), 256, SMEMB, st>>>(
            pwh, pwl, bsh + co, bsl + co, pw_b, spat + co, px + co, nullptr, nullptr,
            Cc, HW, Cc, 0, (long)CHW, (long)CHW);
        // block 1 (2 batches)
        dw_kernel<<<dwGrid2, dwBlock, 0, st>>>(px + co, dw_w + Cc*9, dw_b + Cc, pt + co);
        stats_kernel<<<(2*HW + 255)/256, 256, 0, st>>>(pt + co, ln_w + Cc, ln_b + Cc, bsh + co, bsl + co, 2*HW);
        gemm_ps<2, 1, true, false, true><<<dim3(HW/64, 2, 2), 256, SMEMB, st>>>(
            pwh + Cc*Cc, pwl + Cc*Cc, bsh + co, bsl + co, pw_b + Cc, px + co, nullptr, ysh + co, ysl + co,
            Cc, HW, Cc, 0, (long)CHW, (long)CHW);
        // mask + upsample (2 batches), needs query chain
        cudaStreamWaitEvent(st, evQ, 0);
        gemm_ps<0, 0, false, true, false><<<dim3(HW/64, 3, 2), 256, SMEMB, st>>>(
            qqh + (long)b0*Nq*Cc, qql + (long)b0*Nq*Cc, ysh + co, ysl + co,
            nullptr, nullptr, pm + (long)b0*NHW, nullptr, nullptr,
            Nq, HW, Cc, (long)Nq*Cc, (long)CHW, (long)NHW);
        const long tot4 = 2 * NH2W2 / 4;
        upsample_kernel<<<(unsigned)((tot4 + 255)/256), 256, 0, st>>>(
            pm + (long)b0*NHW, poff + (long)b0*Nq, out + (long)b0*NH2W2, 2*Nq);
    }
    cudaEventRecord(evB, sb);

    // ---- join: stream 0 waits for sb ----
    cudaStreamWaitEvent(0, evB, 0);
}

// round 17
// speedup vs baseline: 1.2751x; 1.0903x over previous
#include <cuda_runtime.h>
#include <cuda_bf16.h>
#include <math.h>
#include <stdint.h>
#include <string.h>

// ---------------- problem constants ----------------
#define Bb 4
#define Cc 256
#define Hh 80
#define Ww 80
#define Nq 300
#define IDim 128
#define HID 512
#define H2 160
#define W2 160
#define HW (Hh*Ww)
#define CHW (Cc*HW)

// ---------------- GEMM tile geometry ----------------
#define RS 40
#define RSB 72
#define STG_A_H 0
#define STG_A_L 10240
#define STG_B_H 20480
#define STG_B_L 25088
#define STG_SZ 29696
#define SMEMB (3*STG_SZ)

// ---------------- device scratch (f32) ----------------
__device__ float g_x[Bb*CHW];
__device__ float g_t[Bb*CHW];
__device__ float g_q4[Bb*Nq*IDim];
__device__ float g_off[Bb*Nq];
__device__ float g_m[Bb*Nq*HW];

// ---------------- device scratch (bf16 hi/lo planes) ----------------
__device__ __nv_bfloat16 g_pwh[2*Cc*Cc],  g_pwl[2*Cc*Cc];
__device__ __nv_bfloat16 g_w1h[Cc*HID],   g_w1l[Cc*HID];
__device__ __nv_bfloat16 g_w2h[HID*HID],  g_w2l[HID*HID];
__device__ __nv_bfloat16 g_w3h[HID*Cc],   g_w3l[HID*Cc];
__device__ __nv_bfloat16 g_qph[Cc*IDim],  g_qpl[Cc*IDim];
__device__ __nv_bfloat16 g_sph[IDim*Cc],  g_spl[IDim*Cc];
__device__ __nv_bfloat16 g_qfh[Bb*Nq*Cc], g_qfl[Bb*Nq*Cc];
__device__ __nv_bfloat16 g_o1h[Bb*Nq*HID],g_o1l[Bb*Nq*HID];
__device__ __nv_bfloat16 g_o2h[Bb*Nq*HID],g_o2l[Bb*Nq*HID];
__device__ __nv_bfloat16 g_o3h[Bb*Nq*Cc], g_o3l[Bb*Nq*Cc];
__device__ __nv_bfloat16 g_o4h[Bb*Nq*IDim],g_o4l[Bb*Nq*IDim];
__device__ __nv_bfloat16 g_qqh[Bb*Nq*Cc], g_qql[Bb*Nq*Cc];
__device__ __nv_bfloat16 g_bsh[Bb*CHW],   g_bsl[Bb*CHW];
__device__ __nv_bfloat16 g_ysh[Bb*CHW],   g_ysl[Bb*CHW];

__device__ __forceinline__ float gelu_f(float x) {
    return 0.5f * x * (1.0f + erff(x * 0.70710678118654752f));
}
__device__ __forceinline__ uint32_t su32(const void* p) {
    return (uint32_t)__cvta_generic_to_shared(p);
}
__device__ __forceinline__ void ldsm4(uint32_t* r, uint32_t addr) {
    asm volatile("ldmatrix.sync.aligned.m8n8.x4.shared.b16 {%0,%1,%2,%3}, [%4];"
        : "=r"(r[0]), "=r"(r[1]), "=r"(r[2]), "=r"(r[3]) : "r"(addr));
}
__device__ __forceinline__ void ldsm4t(uint32_t* r, uint32_t addr) {
    asm volatile("ldmatrix.sync.aligned.m8n8.x4.trans.shared.b16 {%0,%1,%2,%3}, [%4];"
        : "=r"(r[0]), "=r"(r[1]), "=r"(r[2]), "=r"(r[3]) : "r"(addr));
}
__device__ __forceinline__ void mma16816(float* d, const uint32_t* a, const uint32_t* b) {
    asm volatile("mma.sync.aligned.m16n8k16.row.col.f32.bf16.bf16.f32 "
        "{%0,%1,%2,%3}, {%4,%5,%6,%7}, {%8,%9}, {%0,%1,%2,%3};"
        : "+f"(d[0]), "+f"(d[1]), "+f"(d[2]), "+f"(d[3])
        : "r"(a[0]), "r"(a[1]), "r"(a[2]), "r"(a[3]), "r"(b[0]), "r"(b[1]));
}
__device__ __forceinline__ void split_bf16(float x, __nv_bfloat16& hi, __nv_bfloat16& lo) {
    hi = __float2bfloat16(x);
    lo = __float2bfloat16(x - __bfloat162float(hi));
}
__device__ __forceinline__ uint32_t pk2(__nv_bfloat16 a, __nv_bfloat16 b) {
    __nv_bfloat162 t(a, b);
    uint32_t u;
    memcpy(&u, &t, 4);
    return u;
}
__device__ __forceinline__ void cpa16(uint32_t d, const void* s, int bytes) {
    asm volatile("cp.async.cg.shared.global [%0], [%1], 16, %2;"
        :: "r"(d), "l"(s), "r"(bytes));
}
#define CP_COMMIT asm volatile("cp.async.commit_group;")
#define CP_WAIT1  asm volatile("cp.async.wait_group 1;")

// ---------------- depthwise 3x3 conv (SAME/zero-pad), 4 px per thread ----------------
// block (20, 8), grid (1, Hh/8, nb*Cc)
__global__ void dw_kernel(const float* __restrict__ x, const float* __restrict__ w,
                          const float* __restrict__ bia, float* __restrict__ out)
{
    int tx = threadIdx.x;                 // 0..19 -> 4 outputs each
    int hq = blockIdx.y * 8 + threadIdx.y;
    int plane = blockIdx.z;
    int c = plane & (Cc - 1);
    const float* xp = x + (long)plane * HW;
    const float* wp = w + c * 9;
    float b = bia[c];
    float a0 = b, a1 = b, a2 = b, a3 = b;

#pragma unroll
    for (int r = 0; r < 3; r++) {
        int h = hq + r - 1;
        bool hv = (h >= 0) && (h < Hh);
        const float* row = xp + h * Ww;
        float4 v = hv ? *(const float4*)(row + tx * 4) : make_float4(0,0,0,0);
        float lf = (hv && tx > 0)  ? row[tx * 4 - 1] : 0.f;
        float rt = (hv && tx < 19) ? row[tx * 4 + 4] : 0.f;
        float w0 = wp[r*3 + 0], w1 = wp[r*3 + 1], w2 = wp[r*3 + 2];
        a0 += w0 * lf  + w1 * v.x + w2 * v.y;
        a1 += w0 * v.x + w1 * v.y + w2 * v.z;
        a2 += w0 * v.y + w1 * v.z + w2 * v.w;
        a3 += w0 * v.z + w1 * v.w + w2 * rt;
    }
    *(float4*)(out + (long)plane * HW + hq * Ww + tx * 4) = make_float4(a0, a1, a2, a3);
}

// ---------------- LN stats + apply + split, nb batches ----------------
__global__ void stats_kernel(const float* __restrict__ t,
                             const float* __restrict__ lw, const float* __restrict__ lb,
                             __nv_bfloat16* __restrict__ oh, __nv_bfloat16* __restrict__ ol,
                             int npix)
{
    int p = blockIdx.x * blockDim.x + threadIdx.x;
    if (p >= npix) return;
    int bb = p / HW;
    int pix = p - bb * HW;
    const float* base = t + (long)bb * CHW + pix;
    float s = 0.f, s2 = 0.f;
#pragma unroll 8
    for (int c = 0; c < Cc; c++) {
        float v = base[(long)c * HW];
        s += v; s2 += v * v;
    }
    float m = s * (1.0f / Cc);
    float var = s2 * (1.0f / Cc) - m * m;
    float inv = rsqrtf(var + 1e-6f);

    __nv_bfloat16* po = oh + (long)bb * CHW + pix;
    __nv_bfloat16* pl = ol + (long)bb * CHW + pix;
#pragma unroll 4
    for (int c = 0; c < Cc; c++) {
        float v = (base[(long)c * HW] - m) * inv * lw[c] + lb[c];
        __nv_bfloat16 h, l;
        split_bf16(v, h, l);
        po[(long)c * HW] = h;
        pl[(long)c * HW] = l;
    }
}

// ---------------- elementwise split f32 -> bf16 hi/lo ----------------
__global__ void split_k(const float* __restrict__ src,
                        __nv_bfloat16* __restrict__ hi, __nv_bfloat16* __restrict__ lo,
                        int n4)
{
    int i = blockIdx.x * blockDim.x + threadIdx.x;
    if (i >= n4) return;
    float4 v = ((const float4*)src)[i];
    __nv_bfloat16 h0,l0,h1,l1,h2,l2,h3,l3;
    split_bf16(v.x,h0,l0); split_bf16(v.y,h1,l1);
    split_bf16(v.z,h2,l2); split_bf16(v.w,h3,l3);
    ((uint32_t*)hi)[i*2]   = pk2(h0,h1);
    ((uint32_t*)hi)[i*2+1] = pk2(h2,h3);
    ((uint32_t*)lo)[i*2]   = pk2(l0,l1);
    ((uint32_t*)lo)[i*2+1] = pk2(l2,l3);
}

// ---------------- transpose + split ----------------
__global__ void splitT_k(const float* __restrict__ X,
                         __nv_bfloat16* __restrict__ Oh, __nv_bfloat16* __restrict__ Ol,
                         int Krows, int Ncols)
{
    __shared__ float ts[32][33];
    int n0 = blockIdx.x * 32, k0 = blockIdx.y * 32;
    int tx = threadIdx.x, ty = threadIdx.y;

#pragma unroll
    for (int j = 0; j < 4; j++)
        ts[ty + j*8][tx] = X[(long)(k0 + ty + j*8) * Ncols + n0 + tx];
    __syncthreads();

#pragma unroll
    for (int j = 0; j < 4; j++) {
        int n = n0 + ty + j*8;
        int k = k0 + tx;
        float v = ts[tx][ty + j*8];
        __nv_bfloat16 h, l;
        split_bf16(v, h, l);
        Oh[(long)n * Krows + k] = h;
        Ol[(long)n * Krows + k] = l;
    }
}

// ---------------- bf16 tensor-core GEMM, pre-split streaming ----------------
template<int ACT, int BIASM, bool RES, bool OUTF, bool OUTS>
__global__ void __launch_bounds__(256, 2)
gemm_ps(const __nv_bfloat16* __restrict__ Ah_g, const __nv_bfloat16* __restrict__ Al_g,
        const __nv_bfloat16* __restrict__ Bh_g, const __nv_bfloat16* __restrict__ Bl_g,
        const float* __restrict__ bias, const float* __restrict__ resid,
        float* __restrict__ C, __nv_bfloat16* __restrict__ Oh, __nv_bfloat16* __restrict__ Ol,
        int M, int N, int K, long sA, long sB, long sC)
{
    extern __shared__ __align__(16) char dsm[];
    uint32_t sb = su32(dsm);

    int z = blockIdx.z;
    Ah_g += z * sA; Al_g += z * sA;
    Bh_g += z * sB; Bl_g += z * sB;
    if (OUTF) C += z * sC;
    if (OUTS) { Oh += z * sC; Ol += z * sC; }
    const float* R = RES ? (resid + z * sC) : nullptr;

    int m0 = blockIdx.y * 128;
    int n0 = blockIdx.x * 64;
    int tid = threadIdx.x;
    int warp = tid >> 5;
    int lane = tid & 31;
    int wm = warp & 3;
    int wn = warp >> 2;

    int a_r = tid >> 1;
    int a_c = (tid & 1) * 2;
    int b_r = tid >> 3;
    int b_c = tid & 7;

    const int KT = K >> 5;

    auto loadStage = [&](int st, int kb) {
        uint32_t abase = sb + st * STG_SZ;
        bool mok = (m0 + a_r) < M;
        int ab = mok ? 16 : 0;
        const __nv_bfloat16* sh = Ah_g + (long)(m0 + a_r) * K + kb;
        const __nv_bfloat16* sl = Al_g + (long)(m0 + a_r) * K + kb;
        uint32_t dA = abase + a_r * 80 + a_c * 16;
#pragma unroll
        for (int j = 0; j < 2; j++) {
            cpa16(dA + STG_A_H + j * 16, sh + (a_c + j) * 8, ab);
            cpa16(dA + STG_A_L + j * 16, sl + (a_c + j) * 8, ab);
        }
        const __nv_bfloat16* bh = Bh_g + (long)(kb + b_r) * N + n0 + b_c * 8;
        const __nv_bfloat16* bl = Bl_g + (long)(kb + b_r) * N + n0 + b_c * 8;
        uint32_t dB = abase + b_r * 144 + b_c * 16;
        cpa16(dB + STG_B_H, bh, 16);
        cpa16(dB + STG_B_L, bl, 16);
    };

    loadStage(0, 0);
    CP_COMMIT;
    if (KT > 1) loadStage(1, 32);
    CP_COMMIT;

    float acc[2][4][4];
#pragma unroll
    for (int i = 0; i < 2; i++)
#pragma unroll
        for (int j = 0; j < 4; j++)
#pragma unroll
            for (int q = 0; q < 4; q++) acc[i][j][q] = 0.f;

    int a_mrow = lane & 15;
    int a_kh = (lane >> 4) * 8;
    int bg = lane >> 3;
    int b_kr = (bg & 1) * 8 + (lane & 7);
    int b_nc = (bg >> 1) * 8;

    int st = 0;
    for (int kt = 0; kt < KT; kt++) {
        CP_WAIT1;
        __syncthreads();
        if (kt + 2 < KT) loadStage((st + 2 >= 3) ? st - 1 : st + 2, (kt + 2) << 5);
        CP_COMMIT;

        uint32_t base = sb + st * STG_SZ;
#pragma unroll
        for (int half = 0; half < 2; half++) {
            int kc = half * 16;
            uint32_t afr[2][2][4];
#pragma unroll
            for (int s = 0; s < 2; s++) {
                uint32_t ap = base + (s ? STG_A_L : STG_A_H);
#pragma unroll
                for (int mt = 0; mt < 2; mt++)
                    ldsm4(afr[s][mt], ap + ((wm*32 + mt*16 + a_mrow) * RS + kc + a_kh) * 2);
            }
            uint32_t bfr[2][2][4];
#pragma unroll
            for (int p = 0; p < 2; p++) {
                uint32_t boff = ((kc + b_kr) * RSB + wn*32 + p*16 + b_nc) * 2;
                ldsm4t(bfr[p][0], base + STG_B_H + boff);
                ldsm4t(bfr[p][1], base + STG_B_L + boff);
            }
#pragma unroll
            for (int p = 0; p < 2; p++)
#pragma unroll
                for (int mt = 0; mt < 2; mt++) {
                    mma16816(acc[mt][2*p],   afr[0][mt], bfr[p][0]);
                    mma16816(acc[mt][2*p+1], afr[0][mt], bfr[p][0] + 2);
                }
#pragma unroll
            for (int p = 0; p < 2; p++)
#pragma unroll
                for (int mt = 0; mt < 2; mt++) {
                    mma16816(acc[mt][2*p],   afr[0][mt], bfr[p][1]);
                    mma16816(acc[mt][2*p+1], afr[0][mt], bfr[p][1] + 2);
                }
#pragma unroll
            for (int p = 0; p < 2; p++)
#pragma unroll
                for (int mt = 0; mt < 2; mt++) {
                    mma16816(acc[mt][2*p],   afr[1][mt], bfr[p][0]);
                    mma16816(acc[mt][2*p+1], afr[1][mt], bfr[p][0] + 2);
                }
        }
        st++;
        if (st == 3) st = 0;
    }

    // ---- epilogue ----
#pragma unroll
    for (int mt = 0; mt < 2; mt++) {
#pragma unroll
        for (int nt = 0; nt < 4; nt++) {
            int gn = n0 + wn*32 + nt*8 + (lane & 3) * 2;
            float bn0v = 0.f, bn1v = 0.f;
            if (BIASM == 2) { bn0v = bias[gn]; bn1v = bias[gn + 1]; }
#pragma unroll
            for (int h = 0; h < 2; h++) {
                int row = m0 + wm*32 + mt*16 + (lane >> 2) + h*8;
                if (row >= M) continue;
                float x0 = acc[mt][nt][h*2 + 0];
                float x1 = acc[mt][nt][h*2 + 1];
                if (BIASM == 1) { float bm = bias[row]; x0 += bm; x1 += bm; }
                if (BIASM == 2) { x0 += bn0v; x1 += bn1v; }
                if (ACT == 1) { x0 = fmaxf(x0, 0.f); x1 = fmaxf(x1, 0.f); }
                if (ACT == 2) { x0 = gelu_f(x0); x1 = gelu_f(x1); }
                if (RES) {
                    float2 r2 = *(const float2*)&R[(long)row * N + gn];
                    x0 += r2.x; x1 += r2.y;
                }
                if (OUTF) {
                    float2 o; o.x = x0; o.y = x1;
                    *(float2*)&C[(long)row * N + gn] = o;
                }
                if (OUTS) {
                    __nv_bfloat16 h0, l0, h1, l1;
                    split_bf16(x0, h0, l0);
                    split_bf16(x1, h1, l1);
                    *(uint32_t*)&Oh[(long)row * N + gn] = pk2(h0, h1);
                    *(uint32_t*)&Ol[(long)row * N + gn] = pk2(l0, l1);
                }
            }
        }
    }
}

// ---------------- per-query offset ----------------
__global__ void off_kernel(const float* __restrict__ q4, const float* __restrict__ sb,
                           const float* __restrict__ hb, float* __restrict__ off)
{
    int n = blockIdx.x * blockDim.x + threadIdx.x;
    if (n >= Bb*Nq) return;
    float s = hb[0];
#pragma unroll 8
    for (int i = 0; i < IDim; i++) s += q4[(long)n * IDim + i] * sb[i];
    off[n] = s;
}

// ---------------- bilinear 2x upsample + offset (nbn rows) ----------------
__global__ void upsample_kernel(const float* __restrict__ m, const float* __restrict__ off,
                                float* __restrict__ out, int nbn)
{
    long idx = (long)blockIdx.x * blockDim.x + threadIdx.x;
    const long tot4 = (long)nbn * H2 * (W2 / 4);
    if (idx >= tot4) return;
    int wq4 = (int)(idx % (W2 / 4)) * 4;
    int h2 = (int)((idx / (W2 / 4)) % H2);
    long bn = idx / ((long)(W2 / 4) * H2);

    float fh = h2 * 0.5f - 0.25f;
    int h0f = (int)floorf(fh);
    float wh = fh - (float)h0f;
    int h0 = max(h0f, 0), h1 = min(h0f + 1, Hh - 1);

    const float* r0 = m + bn * (long)HW + h0 * Ww;
    const float* r1 = m + bn * (long)HW + h1 * Ww;
    float o = off[bn];

    float r[4];
#pragma unroll
    for (int j = 0; j < 4; j++) {
        int w2 = wq4 + j;
        float fw = w2 * 0.5f - 0.25f;
        int w0f = (int)floorf(fw);
        float ww = fw - (float)w0f;
        int w0 = max(w0f, 0), w1 = min(w0f + 1, Ww - 1);
        float t0 = r0[w0] * (1.f - ww) + r0[w1] * ww;
        float t1 = r1[w0] * (1.f - ww) + r1[w1] * ww;
        r[j] = t0 * (1.f - wh) + t1 * wh + o;
    }
    float4 v = make_float4(r[0], r[1], r[2], r[3]);
    *(float4*)(out + bn * (long)(H2 * W2) + (long)h2 * W2 + wq4) = v;
}

// ---------------- launcher ----------------
extern "C" void kernel_launch(void* const* d_in, const int* in_sizes, int n_in,
                              void* d_out, int out_size)
{
    const float* spat    = (const float*)d_in[0];
    const float* qf      = (const float*)d_in[1];
    const float* dw_w    = (const float*)d_in[2];
    const float* dw_b    = (const float*)d_in[3];
    const float* ln_w    = (const float*)d_in[4];
    const float* ln_b    = (const float*)d_in[5];
    const float* pw_w    = (const float*)d_in[6];
    const float* pw_b    = (const float*)d_in[7];
    const float* sproj_w = (const float*)d_in[8];
    const float* sproj_b = (const float*)d_in[9];
    const float* mlp_w1  = (const float*)d_in[10];
    const float* mlp_b1  = (const float*)d_in[11];
    const float* mlp_w2  = (const float*)d_in[12];
    const float* mlp_b2  = (const float*)d_in[13];
    const float* mlp_w3  = (const float*)d_in[14];
    const float* mlp_b3  = (const float*)d_in[15];
    const float* qproj_w = (const float*)d_in[16];
    const float* qproj_b = (const float*)d_in[17];
    const float* head_b  = (const float*)d_in[18];
    float* out = (float*)d_out;

    float *px, *pt, *pq4, *poff, *pm;
    cudaGetSymbolAddress((void**)&px,   g_x);
    cudaGetSymbolAddress((void**)&pt,   g_t);
    cudaGetSymbolAddress((void**)&pq4,  g_q4);
    cudaGetSymbolAddress((void**)&poff, g_off);
    cudaGetSymbolAddress((void**)&pm,   g_m);

    __nv_bfloat16 *pwh,*pwl,*w1h,*w1l,*w2h,*w2l,*w3h,*w3l,*qph,*qpl,*sph,*spl;
    __nv_bfloat16 *qfh,*qfl,*o1h,*o1l,*o2h,*o2l,*o3h,*o3l,*o4h,*o4l,*qqh,*qql,*bsh,*bsl,*ysh,*ysl;
    cudaGetSymbolAddress((void**)&pwh, g_pwh); cudaGetSymbolAddress((void**)&pwl, g_pwl);
    cudaGetSymbolAddress((void**)&w1h, g_w1h); cudaGetSymbolAddress((void**)&w1l, g_w1l);
    cudaGetSymbolAddress((void**)&w2h, g_w2h); cudaGetSymbolAddress((void**)&w2l, g_w2l);
    cudaGetSymbolAddress((void**)&w3h, g_w3h); cudaGetSymbolAddress((void**)&w3l, g_w3l);
    cudaGetSymbolAddress((void**)&qph, g_qph); cudaGetSymbolAddress((void**)&qpl, g_qpl);
    cudaGetSymbolAddress((void**)&sph, g_sph); cudaGetSymbolAddress((void**)&spl, g_spl);
    cudaGetSymbolAddress((void**)&qfh, g_qfh); cudaGetSymbolAddress((void**)&qfl, g_qfl);
    cudaGetSymbolAddress((void**)&o1h, g_o1h); cudaGetSymbolAddress((void**)&o1l, g_o1l);
    cudaGetSymbolAddress((void**)&o2h, g_o2h); cudaGetSymbolAddress((void**)&o2l, g_o2l);
    cudaGetSymbolAddress((void**)&o3h, g_o3h); cudaGetSymbolAddress((void**)&o3l, g_o3l);
    cudaGetSymbolAddress((void**)&o4h, g_o4h); cudaGetSymbolAddress((void**)&o4l, g_o4l);
    cudaGetSymbolAddress((void**)&qqh, g_qqh); cudaGetSymbolAddress((void**)&qql, g_qql);
    cudaGetSymbolAddress((void**)&bsh, g_bsh); cudaGetSymbolAddress((void**)&bsl, g_bsl);
    cudaGetSymbolAddress((void**)&ysh, g_ysh); cudaGetSymbolAddress((void**)&ysl, g_ysl);

    cudaFuncSetAttribute(gemm_ps<1,2,false,false,true>,  cudaFuncAttributeMaxDynamicSharedMemorySize, SMEMB);
    cudaFuncSetAttribute(gemm_ps<2,1,true,true,false>,   cudaFuncAttributeMaxDynamicSharedMemorySize, SMEMB);
    cudaFuncSetAttribute(gemm_ps<2,1,true,false,true>,   cudaFuncAttributeMaxDynamicSharedMemorySize, SMEMB);
    cudaFuncSetAttribute(gemm_ps<0,2,false,false,true>,  cudaFuncAttributeMaxDynamicSharedMemorySize, SMEMB);
    cudaFuncSetAttribute(gemm_ps<0,2,false,true,true>,   cudaFuncAttributeMaxDynamicSharedMemorySize, SMEMB);
    cudaFuncSetAttribute(gemm_ps<0,0,false,false,true>,  cudaFuncAttributeMaxDynamicSharedMemorySize, SMEMB);
    cudaFuncSetAttribute(gemm_ps<0,0,false,true,false>,  cudaFuncAttributeMaxDynamicSharedMemorySize, SMEMB);

    dim3 dwBlock(20, 8);
    dim3 dwGrid2(1, Hh / 8, 2 * Cc);   // 2 batches per chain
    dim3 tBlock(32, 8);
    const int Mq = Bb * Nq;
    const long NHW = (long)Nq * HW;
    const long NH2W2 = (long)Nq * H2 * W2;

    // ---- streams & events: created EXACTLY ONCE (teardown-safe footprint) ----
    static bool s_init = false;
    static cudaStream_t sq, sb;
    static cudaEvent_t evFork, evW, evQ, evB;
    if (!s_init) {
        cudaStreamCreateWithFlags(&sq, cudaStreamNonBlocking);
        cudaStreamCreateWithFlags(&sb, cudaStreamNonBlocking);
        cudaEventCreateWithFlags(&evFork, cudaEventDisableTiming);
        cudaEventCreateWithFlags(&evW,    cudaEventDisableTiming);
        cudaEventCreateWithFlags(&evQ,    cudaEventDisableTiming);
        cudaEventCreateWithFlags(&evB,    cudaEventDisableTiming);
        s_init = true;
    }

    // ---- fork immediately; pw weight split hides on the query stream ----
    cudaEventRecord(evFork, 0);
    cudaStreamWaitEvent(sq, evFork, 0);
    cudaStreamWaitEvent(sb, evFork, 0);

    // ======== query stream: pw weight split first, then query chain ========
    split_k<<<(2*Cc*Cc/4 + 255)/256, 256, 0, sq>>>(pw_w, pwh, pwl, 2*Cc*Cc/4);
    cudaEventRecord(evW, sq);

    split_k<<<(Mq*Cc/4 + 255)/256, 256, 0, sq>>>(qf, qfh, qfl, Mq*Cc/4);
    splitT_k<<<dim3(Cc/32, HID/32, 1), tBlock, 0, sq>>>(mlp_w1, w1h, w1l, HID, Cc);
    splitT_k<<<dim3(HID/32, HID/32, 1), tBlock, 0, sq>>>(mlp_w2, w2h, w2l, HID, HID);
    splitT_k<<<dim3(HID/32, Cc/32, 1), tBlock, 0, sq>>>(mlp_w3, w3h, w3l, Cc, HID);
    splitT_k<<<dim3(Cc/32, IDim/32, 1), tBlock, 0, sq>>>(qproj_w, qph, qpl, IDim, Cc);
    split_k<<<(IDim*Cc/4 + 255)/256, 256, 0, sq>>>(sproj_w, sph, spl, IDim*Cc/4);

    gemm_ps<1, 2, false, false, true><<<dim3(HID/64, 10, 1), 256, SMEMB, sq>>>(
        qfh, qfl, w1h, w1l, mlp_b1, nullptr, nullptr, o1h, o1l,
        Mq, HID, Cc, 0, 0, 0);
    gemm_ps<1, 2, false, false, true><<<dim3(HID/64, 10, 1), 256, SMEMB, sq>>>(
        o1h, o1l, w2h, w2l, mlp_b2, nullptr, nullptr, o2h, o2l,
        Mq, HID, HID, 0, 0, 0);
    gemm_ps<0, 2, false, false, true><<<dim3(Cc/64, 10, 1), 256, SMEMB, sq>>>(
        o2h, o2l, w3h, w3l, mlp_b3, nullptr, nullptr, o3h, o3l,
        Mq, Cc, HID, 0, 0, 0);
    gemm_ps<0, 2, false, true, true><<<dim3(IDim/64, 10, 1), 256, SMEMB, sq>>>(
        o3h, o3l, qph, qpl, qproj_b, nullptr, pq4, o4h, o4l,
        Mq, IDim, Cc, 0, 0, 0);
    gemm_ps<0, 0, false, false, true><<<dim3(Cc/64, 10, 1), 256, SMEMB, sq>>>(
        o4h, o4l, sph, spl, nullptr, nullptr, nullptr, qqh, qql,
        Mq, Cc, IDim, 0, 0, 0);
    off_kernel<<<(Mq + 255)/256, 256, 0, sq>>>(pq4, sproj_b, head_b, poff);
    cudaEventRecord(evQ, sq);

    // ======== half-batch spatial chains (z=2): {0,1} on stream 0, {2,3} on sb ========
    for (int g = 0; g < 2; g++) {
        cudaStream_t st = (g == 0) ? (cudaStream_t)0 : sb;
        int b0 = g * 2;
        long co = (long)b0 * CHW;
        // block 0 (2 batches): dw+stats run before the weight split completes
        dw_kernel<<<dwGrid2, dwBlock, 0, st>>>(spat + co, dw_w, dw_b, pt + co);
        stats_kernel<<<(2*HW + 255)/256, 256, 0, st>>>(pt + co, ln_w, ln_b, bsh + co, bsl + co, 2*HW);
        cudaStreamWaitEvent(st, evW, 0);
        gemm_ps<2, 1, true, true, false><<<dim3(HW/64, 2, 2), 256, SMEMB, st>>>(
            pwh, pwl, bsh + co, bsl + co, pw_b, spat + co, px + co, nullptr, nullptr,
            Cc, HW, Cc, 0, (long)CHW, (long)CHW);
        // block 1 (2 batches)
        dw_kernel<<<dwGrid2, dwBlock, 0, st>>>(px + co, dw_w + Cc*9, dw_b + Cc, pt + co);
        stats_kernel<<<(2*HW + 255)/256, 256, 0, st>>>(pt + co, ln_w + Cc, ln_b + Cc, bsh + co, bsl + co, 2*HW);
        gemm_ps<2, 1, true, false, true><<<dim3(HW/64, 2, 2), 256, SMEMB, st>>>(
            pwh + Cc*Cc, pwl + Cc*Cc, bsh + co, bsl + co, pw_b + Cc, px + co, nullptr, ysh + co, ysl + co,
            Cc, HW, Cc, 0, (long)CHW, (long)CHW);
        // mask + upsample (2 batches), needs query chain
        cudaStreamWaitEvent(st, evQ, 0);
        gemm_ps<0, 0, false, true, false><<<dim3(HW/64, 3, 2), 256, SMEMB, st>>>(
            qqh + (long)b0*Nq*Cc, qql + (long)b0*Nq*Cc, ysh + co, ysl + co,
            nullptr, nullptr, pm + (long)b0*NHW, nullptr, nullptr,
            Nq, HW, Cc, (long)Nq*Cc, (long)CHW, (long)NHW);
        const long tot4 = 2 * NH2W2 / 4;
        upsample_kernel<<<(unsigned)((tot4 + 255)/256), 256, 0, st>>>(
            pm + (long)b0*NHW, poff + (long)b0*Nq, out + (long)b0*NH2W2, 2*Nq);
    }
    cudaEventRecord(evB, sb);

    // ---- join: stream 0 waits for sb ----
    cudaStreamWaitEvent(0, evB, 0);
}